// round 4
// baseline (speedup 1.0000x reference)
#include <cuda_runtime.h>
#include <cstdint>

// PrototypeLoss: loss = 1 - (1/B) * sum_c || sum_{i: label_i=c} normalize(f_i) ||
// B = 262144, D = 256, C = 1000 (fixed shapes for this problem)
//
// Two launches per call:
//   scatter_kernel: bucket row indices by class (int atomics only),
//                   inline int64/int32 label-dtype detection per block.
//   class_kernel:   one block per class; gather rows (coalesced 1KB each),
//                   normalize per-row via warp reduction, accumulate class sum,
//                   sum-of-norms via scalar atomic; last-done block writes the
//                   output. All device state is self-resetting so the kernel
//                   sequence is graph-replayable with zero init launches
//                   (__device__ globals start zeroed at module load).

static constexpr int C_CLS = 1000;
static constexpr int D_DIM = 256;
static constexpr int CAP   = 1024;   // bucket capacity (expected ~262/class)

__device__ int      g_cnt[C_CLS];        // zero at load; reset by class_kernel
__device__ int      g_idx[C_CLS * CAP];
__device__ float    g_acc;               // zero at load; reset by last block
__device__ unsigned g_done;              // zero at load; reset by last block

// ---------------------------------------------------------------------------
// Scatter row indices into per-class buckets.
// Label dtype (int64 vs int32) detected per block: for little-endian int64
// labels in [0,1000), every odd 32-bit word is 0. Under int32 random labels,
// 64 probed words all being zero has probability ~1e-192. Probed words lie
// within the first 1KB, valid for either dtype.
// ---------------------------------------------------------------------------
__global__ __launch_bounds__(512) void scatter_kernel(const void* __restrict__ labels,
                                                      int B) {
    __shared__ int s_is64;
    const int* lbl32 = (const int*)labels;
    if (threadIdx.x < 32) {
        int v = lbl32[2 * threadIdx.x + 1] | lbl32[2 * threadIdx.x + 65];
        unsigned any = __ballot_sync(0xffffffffu, v != 0);
        if (threadIdx.x == 0) s_is64 = (any == 0u) ? 1 : 0;
    }
    __syncthreads();

    int i = blockIdx.x * blockDim.x + threadIdx.x;
    if (i >= B) return;
    int l;
    if (s_is64) l = (int)((const long long*)labels)[i];
    else        l = lbl32[i];
    if (l < 0 || l >= C_CLS) return;     // defensive
    int pos = atomicAdd(&g_cnt[l], 1);
    if (pos < CAP) g_idx[l * CAP + pos] = i;
}

// ---------------------------------------------------------------------------
// One block per class; 8 warps, each warp owns a disjoint set of rows.
// Hot loop unrolled x2 rows/warp: 4 outstanding float4 loads, two overlapped
// shuffle-reduction chains. No block barriers in the hot loop.
// ---------------------------------------------------------------------------
__global__ __launch_bounds__(256) void class_kernel(const float* __restrict__ f,
                                                    float* __restrict__ out,
                                                    int B) {
    __shared__ float sm[8][8][33];   // [warp][slot][lane], padded
    int c    = blockIdx.x;
    int n    = g_cnt[c];
    if (n > CAP) n = CAP;
    int warp = threadIdx.x >> 5;
    int lane = threadIdx.x & 31;

    float a0 = 0.f, a1 = 0.f, a2 = 0.f, a3 = 0.f;
    float a4 = 0.f, a5 = 0.f, a6 = 0.f, a7 = 0.f;
    const int* __restrict__ idx = &g_idx[c * CAP];

    int r = warp;
    for (; r + 8 < n; r += 16) {
        int row0 = idx[r];
        int row1 = idx[r + 8];
        const float4* __restrict__ p0 = (const float4*)(f + (size_t)row0 * D_DIM);
        const float4* __restrict__ p1 = (const float4*)(f + (size_t)row1 * D_DIM);
        float4 x0 = p0[lane];
        float4 y0 = p0[lane + 32];
        float4 x1 = p1[lane];
        float4 y1 = p1[lane + 32];
        float s0 = x0.x * x0.x + x0.y * x0.y + x0.z * x0.z + x0.w * x0.w
                 + y0.x * y0.x + y0.y * y0.y + y0.z * y0.z + y0.w * y0.w;
        float s1 = x1.x * x1.x + x1.y * x1.y + x1.z * x1.z + x1.w * x1.w
                 + y1.x * y1.x + y1.y * y1.y + y1.z * y1.z + y1.w * y1.w;
        #pragma unroll
        for (int o = 16; o; o >>= 1) {
            s0 += __shfl_xor_sync(0xffffffffu, s0, o);
            s1 += __shfl_xor_sync(0xffffffffu, s1, o);
        }
        float i0 = rsqrtf(fmaxf(s0, 1e-24f));
        float i1 = rsqrtf(fmaxf(s1, 1e-24f));
        a0 += x0.x * i0 + x1.x * i1;  a1 += x0.y * i0 + x1.y * i1;
        a2 += x0.z * i0 + x1.z * i1;  a3 += x0.w * i0 + x1.w * i1;
        a4 += y0.x * i0 + y1.x * i1;  a5 += y0.y * i0 + y1.y * i1;
        a6 += y0.z * i0 + y1.z * i1;  a7 += y0.w * i0 + y1.w * i1;
    }
    if (r < n) {
        int row = idx[r];
        const float4* __restrict__ p = (const float4*)(f + (size_t)row * D_DIM);
        float4 x = p[lane];
        float4 y = p[lane + 32];
        float s = x.x * x.x + x.y * x.y + x.z * x.z + x.w * x.w
                + y.x * y.x + y.y * y.y + y.z * y.z + y.w * y.w;
        #pragma unroll
        for (int o = 16; o; o >>= 1) s += __shfl_xor_sync(0xffffffffu, s, o);
        float iv = rsqrtf(fmaxf(s, 1e-24f));
        a0 += x.x * iv; a1 += x.y * iv; a2 += x.z * iv; a3 += x.w * iv;
        a4 += y.x * iv; a5 += y.y * iv; a6 += y.z * iv; a7 += y.w * iv;
    }

    sm[warp][0][lane] = a0; sm[warp][1][lane] = a1;
    sm[warp][2][lane] = a2; sm[warp][3][lane] = a3;
    sm[warp][4][lane] = a4; sm[warp][5][lane] = a5;
    sm[warp][6][lane] = a6; sm[warp][7][lane] = a7;
    __syncthreads();

    if (warp == 0) {
        float ss = 0.f;
        #pragma unroll
        for (int k = 0; k < 8; k++) {
            float t = 0.f;
            #pragma unroll
            for (int w = 0; w < 8; w++) t += sm[w][k][lane];
            ss += t * t;
        }
        #pragma unroll
        for (int o = 16; o; o >>= 1) ss += __shfl_xor_sync(0xffffffffu, ss, o);

        if (lane == 0) {
            atomicAdd(&g_acc, sqrtf(ss));
            g_cnt[c] = 0;                       // self-reset for next replay
            __threadfence();
            unsigned t = atomicAdd(&g_done, 1u);
            if (t == (unsigned)(gridDim.x - 1)) {
                __threadfence();
                float acc = *((volatile float*)&g_acc);
                out[0] = 1.0f - acc / (float)B;
                g_acc  = 0.0f;                  // self-reset
                g_done = 0u;
            }
        }
    }
}

extern "C" void kernel_launch(void* const* d_in, const int* in_sizes, int n_in,
                              void* d_out, int out_size) {
    const float* features = (const float*)d_in[0];
    const void*  labels   = d_in[1];
    int B = in_sizes[1];                                    // 262144 labels
    if (B * D_DIM != in_sizes[0]) B = in_sizes[0] / D_DIM;  // defensive

    scatter_kernel<<<(B + 511) / 512, 512>>>(labels, B);
    class_kernel<<<C_CLS, 256>>>(features, (float*)d_out, B);
}

// round 5
// speedup vs baseline: 1.0294x; 1.0294x over previous
#include <cuda_runtime.h>
#include <cstdint>

// PrototypeLoss: loss = 1 - (1/B) * sum_c || sum_{i: label_i=c} normalize(f_i) ||
// B = 262144, D = 256, C = 1000 (fixed shapes)
//
// Two graph nodes per call:
//   scatter_kernel : bucket row indices by class (vectorized label loads,
//                    inline int64/int32 dtype probe).
//   class_kernel   : NSEG segment-blocks per class accumulate partial class
//                    sums (float RED.ADD into g_sum); per-class done-ticket
//                    elects a finisher that computes the class norm; a global
//                    ticket elects the output writer. All device state
//                    self-resets => graph-replayable with no init kernel.

static constexpr int C_CLS = 1000;
static constexpr int D_DIM = 256;
static constexpr int CAP   = 1024;   // bucket capacity (expected ~262/class)
static constexpr int NSEG  = 8;      // segment blocks per class

__device__ int      g_cnt[C_CLS];          // zeroed at load; reset by finisher
__device__ int      g_idx[C_CLS * CAP];
__device__ float    g_sum[C_CLS * D_DIM];  // zeroed at load; reset by finisher
__device__ int      g_cdone[C_CLS];        // per-class ticket
__device__ float    g_acc;
__device__ unsigned g_done;

// ---------------------------------------------------------------------------
// Scatter: 4 labels per thread. int64-vs-int32 probe: for LE int64 labels in
// [0,1000) every odd 32-bit word is 0; 64 random int32 labels all being zero
// has probability ~1e-192. Probed words lie in the first 1KB (valid for both).
// ---------------------------------------------------------------------------
__global__ __launch_bounds__(512) void scatter_kernel(const void* __restrict__ labels,
                                                      int B) {
    __shared__ int s_is64;
    const int* lbl32 = (const int*)labels;
    if (threadIdx.x < 32) {
        int v = lbl32[2 * threadIdx.x + 1] | lbl32[2 * threadIdx.x + 65];
        unsigned any = __ballot_sync(0xffffffffu, v != 0);
        if (threadIdx.x == 0) s_is64 = (any == 0u) ? 1 : 0;
    }
    __syncthreads();
    const int is64 = s_is64;

    int base = (blockIdx.x * 512 + threadIdx.x) * 4;
    if (base + 3 < B) {
        int l0, l1, l2, l3;
        if (is64) {
            const longlong2* p = (const longlong2*)labels;
            longlong2 u0 = p[(base >> 1)];
            longlong2 u1 = p[(base >> 1) + 1];
            l0 = (int)u0.x; l1 = (int)u0.y; l2 = (int)u1.x; l3 = (int)u1.y;
        } else {
            int4 u = ((const int4*)labels)[base >> 2];
            l0 = u.x; l1 = u.y; l2 = u.z; l3 = u.w;
        }
        if ((unsigned)l0 < (unsigned)C_CLS) {
            int p0 = atomicAdd(&g_cnt[l0], 1); if (p0 < CAP) g_idx[l0 * CAP + p0] = base;
        }
        if ((unsigned)l1 < (unsigned)C_CLS) {
            int p1 = atomicAdd(&g_cnt[l1], 1); if (p1 < CAP) g_idx[l1 * CAP + p1] = base + 1;
        }
        if ((unsigned)l2 < (unsigned)C_CLS) {
            int p2 = atomicAdd(&g_cnt[l2], 1); if (p2 < CAP) g_idx[l2 * CAP + p2] = base + 2;
        }
        if ((unsigned)l3 < (unsigned)C_CLS) {
            int p3 = atomicAdd(&g_cnt[l3], 1); if (p3 < CAP) g_idx[l3 * CAP + p3] = base + 3;
        }
    } else {
        for (int i = base; i < B; i++) {
            int l = is64 ? (int)((const long long*)labels)[i] : lbl32[i];
            if ((unsigned)l < (unsigned)C_CLS) {
                int p = atomicAdd(&g_cnt[l], 1);
                if (p < CAP) g_idx[l * CAP + p] = i;
            }
        }
    }
}

// ---------------------------------------------------------------------------
// class_kernel: block b -> class c = b/NSEG, segment s = b%NSEG.
// Segment s processes bucket entries e = s + NSEG*j; warp w takes j = w mod 4.
// Each row: 2x float4 per lane (coalesced 1KB), warp-shuffle sumsq, rsqrt,
// accumulate 8 regs/lane. 2-row unroll for MLP. No block barrier in hot loop.
// ---------------------------------------------------------------------------
__global__ __launch_bounds__(128) void class_kernel(const float* __restrict__ f,
                                                    float* __restrict__ out,
                                                    int B) {
    __shared__ float sm[4][8][33];   // [warp][slot][lane], padded
    __shared__ int   s_fin;
    const int b    = blockIdx.x;
    const int c    = b / NSEG;
    const int seg  = b - c * NSEG;
    int n = g_cnt[c];
    if (n > CAP) n = CAP;
    const int warp = threadIdx.x >> 5;
    const int lane = threadIdx.x & 31;

    float a0 = 0.f, a1 = 0.f, a2 = 0.f, a3 = 0.f;
    float a4 = 0.f, a5 = 0.f, a6 = 0.f, a7 = 0.f;
    const int* __restrict__ idx = &g_idx[c * CAP];

    int j = warp;
    for (; seg + ((j + 4) << 3) < n; j += 8) {
        int e0 = seg + (j << 3);
        int e1 = seg + ((j + 4) << 3);
        int row0 = idx[e0];
        int row1 = idx[e1];
        const float4* __restrict__ p0 = (const float4*)(f + (size_t)row0 * D_DIM);
        const float4* __restrict__ p1 = (const float4*)(f + (size_t)row1 * D_DIM);
        float4 x0 = p0[lane];
        float4 y0 = p0[lane + 32];
        float4 x1 = p1[lane];
        float4 y1 = p1[lane + 32];
        float s0 = x0.x * x0.x + x0.y * x0.y + x0.z * x0.z + x0.w * x0.w
                 + y0.x * y0.x + y0.y * y0.y + y0.z * y0.z + y0.w * y0.w;
        float s1 = x1.x * x1.x + x1.y * x1.y + x1.z * x1.z + x1.w * x1.w
                 + y1.x * y1.x + y1.y * y1.y + y1.z * y1.z + y1.w * y1.w;
        #pragma unroll
        for (int o = 16; o; o >>= 1) {
            s0 += __shfl_xor_sync(0xffffffffu, s0, o);
            s1 += __shfl_xor_sync(0xffffffffu, s1, o);
        }
        float i0 = rsqrtf(fmaxf(s0, 1e-24f));
        float i1 = rsqrtf(fmaxf(s1, 1e-24f));
        a0 += x0.x * i0 + x1.x * i1;  a1 += x0.y * i0 + x1.y * i1;
        a2 += x0.z * i0 + x1.z * i1;  a3 += x0.w * i0 + x1.w * i1;
        a4 += y0.x * i0 + y1.x * i1;  a5 += y0.y * i0 + y1.y * i1;
        a6 += y0.z * i0 + y1.z * i1;  a7 += y0.w * i0 + y1.w * i1;
    }
    for (; seg + (j << 3) < n; j += 4) {
        int row = idx[seg + (j << 3)];
        const float4* __restrict__ p = (const float4*)(f + (size_t)row * D_DIM);
        float4 x = p[lane];
        float4 y = p[lane + 32];
        float s = x.x * x.x + x.y * x.y + x.z * x.z + x.w * x.w
                + y.x * y.x + y.y * y.y + y.z * y.z + y.w * y.w;
        #pragma unroll
        for (int o = 16; o; o >>= 1) s += __shfl_xor_sync(0xffffffffu, s, o);
        float iv = rsqrtf(fmaxf(s, 1e-24f));
        a0 += x.x * iv; a1 += x.y * iv; a2 += x.z * iv; a3 += x.w * iv;
        a4 += y.x * iv; a5 += y.y * iv; a6 += y.z * iv; a7 += y.w * iv;
    }

    // warp accumulators -> smem; lane l slot k: element 4l+k (x) / 128+4l+k (y)
    sm[warp][0][lane] = a0; sm[warp][1][lane] = a1;
    sm[warp][2][lane] = a2; sm[warp][3][lane] = a3;
    sm[warp][4][lane] = a4; sm[warp][5][lane] = a5;
    sm[warp][6][lane] = a6; sm[warp][7][lane] = a7;
    __syncthreads();

    // thread t: elements t and t+128; combine 4 warps; RED.ADD into g_sum
    {
        int t  = threadIdx.x;                 // 0..127
        int l0 = t >> 2, k0 = t & 3;          // element t    -> slot k0
        float v0 = sm[0][k0][l0] + sm[1][k0][l0] + sm[2][k0][l0] + sm[3][k0][l0];
        float v1 = sm[0][4 + k0][l0] + sm[1][4 + k0][l0]
                 + sm[2][4 + k0][l0] + sm[3][4 + k0][l0];
        atomicAdd(&g_sum[c * D_DIM + t], v0);
        atomicAdd(&g_sum[c * D_DIM + t + 128], v1);
    }

    __threadfence();          // publish this block's REDs (all threads)
    __syncthreads();
    if (threadIdx.x == 0) {
        int p = atomicAdd(&g_cdone[c], 1);
        s_fin = (p == NSEG - 1) ? 1 : 0;
    }
    __syncthreads();

    if (s_fin) {
        __threadfence();
        int t = threadIdx.x;
        volatile float* gs = g_sum;
        float v0 = gs[c * D_DIM + t];
        float v1 = gs[c * D_DIM + t + 128];
        g_sum[c * D_DIM + t] = 0.f;            // self-reset
        g_sum[c * D_DIM + t + 128] = 0.f;
        float ss = v0 * v0 + v1 * v1;
        #pragma unroll
        for (int o = 16; o; o >>= 1) ss += __shfl_xor_sync(0xffffffffu, ss, o);
        if ((threadIdx.x & 31) == 0) sm[0][0][threadIdx.x >> 5] = ss;
        __syncthreads();
        if (threadIdx.x == 0) {
            float tot = sm[0][0][0] + sm[0][0][1] + sm[0][0][2] + sm[0][0][3];
            atomicAdd(&g_acc, sqrtf(tot));
            g_cnt[c]   = 0;                    // self-reset
            g_cdone[c] = 0;
            __threadfence();
            unsigned q = atomicAdd(&g_done, 1u);
            if (q == (unsigned)(C_CLS - 1)) {
                __threadfence();
                float acc = *((volatile float*)&g_acc);
                out[0] = 1.0f - acc / (float)B;
                g_acc  = 0.0f;
                g_done = 0u;
            }
        }
    }
}

extern "C" void kernel_launch(void* const* d_in, const int* in_sizes, int n_in,
                              void* d_out, int out_size) {
    const float* features = (const float*)d_in[0];
    const void*  labels   = d_in[1];
    int B = in_sizes[1];                                    // 262144 labels
    if (B * D_DIM != in_sizes[0]) B = in_sizes[0] / D_DIM;  // defensive

    scatter_kernel<<<(B + 2047) / 2048, 512>>>(labels, B);
    class_kernel<<<C_CLS * NSEG, 128>>>(features, (float*)d_out, B);
}